// round 1
// baseline (speedup 1.0000x reference)
#include <cuda_runtime.h>
#include <math.h>

#define BATCH 2
#define CDIM 192
#define HH 192
#define WW 192
#define HWSZ (HH*WW)      // 36864
#define OC3 (3*CDIM)      // 576
#define NH 4
#define HD 48

// ---- scratch (device globals; no allocations allowed) ----
__device__ float g_qkv[(long)BATCH*OC3*HWSZ];   // after 1x1 conv
__device__ float g_dw [(long)BATCH*OC3*HWSZ];   // after depthwise conv
__device__ float g_sumsq[BATCH*2*CDIM];          // per-channel sum of squares (q,k)
__device__ float g_attn [BATCH*NH*HD*HD];        // raw q.k^T accumulators
__device__ float g_attn_s[BATCH*NH*HD*HD];       // softmaxed
__device__ float g_W2[BATCH*CDIM*CDIM];          // w_proj @ blockdiag(attn)

// ---------------------------------------------------------------
// zero the atomic accumulators (graph replays need this each call)
// ---------------------------------------------------------------
__global__ void zero_kernel() {
    int i = blockIdx.x * blockDim.x + threadIdx.x;
    if (i < BATCH*2*CDIM)    g_sumsq[i] = 0.f;
    if (i < BATCH*NH*HD*HD)  g_attn[i]  = 0.f;
}

// ---------------------------------------------------------------
// SGEMM: C[M,HW] = A[M,192] @ B[192,HW], row-major, K=192 fixed.
// Tile 64x128xBK16, 256 threads, microtile 8x4. All dims divide evenly.
// grid: (HW/128, M/64, BATCH)
// ---------------------------------------------------------------
__global__ __launch_bounds__(256) void sgemm_kernel(
    const float* __restrict__ A, const float* __restrict__ Bm, float* __restrict__ Cm,
    long aStride, long bStride, long cStride)
{
    __shared__ float As[16][68];   // padded, float4-aligned rows
    __shared__ float Bs[16][128];

    const float* Ab = A  + (long)blockIdx.z * aStride;
    const float* Bb = Bm + (long)blockIdx.z * bStride;
    float*       Cb = Cm + (long)blockIdx.z * cStride;

    const int row0 = blockIdx.y * 64;
    const int col0 = blockIdx.x * 128;
    const int t  = threadIdx.x;
    const int ar = t >> 2, ac = (t & 3) * 4;    // A tile load: 64 rows x 16 k
    const int br = t >> 5, bc = (t & 31) * 4;   // B tile load: 16 k x 128 cols
    const int ty = t >> 5, tx = t & 31;         // microtile coords

    float acc[8][4];
#pragma unroll
    for (int i = 0; i < 8; i++)
#pragma unroll
        for (int j = 0; j < 4; j++) acc[i][j] = 0.f;

    for (int k0 = 0; k0 < 192; k0 += 16) {
        float4 a4 = *(const float4*)(Ab + (long)(row0 + ar) * 192 + k0 + ac);
        float4 b0 = *(const float4*)(Bb + (long)(k0 + br) * HWSZ + col0 + bc);
        float4 b1 = *(const float4*)(Bb + (long)(k0 + br + 8) * HWSZ + col0 + bc);
        As[ac + 0][ar] = a4.x; As[ac + 1][ar] = a4.y;
        As[ac + 2][ar] = a4.z; As[ac + 3][ar] = a4.w;
        *(float4*)&Bs[br][bc]     = b0;
        *(float4*)&Bs[br + 8][bc] = b1;
        __syncthreads();
#pragma unroll
        for (int kk = 0; kk < 16; kk++) {
            float4 a0 = *(const float4*)&As[kk][ty * 8];
            float4 a1 = *(const float4*)&As[kk][ty * 8 + 4];
            float4 bv = *(const float4*)&Bs[kk][tx * 4];
            float av[8] = {a0.x, a0.y, a0.z, a0.w, a1.x, a1.y, a1.z, a1.w};
            float bw[4] = {bv.x, bv.y, bv.z, bv.w};
#pragma unroll
            for (int i = 0; i < 8; i++)
#pragma unroll
                for (int j = 0; j < 4; j++)
                    acc[i][j] = fmaf(av[i], bw[j], acc[i][j]);
        }
        __syncthreads();
    }

#pragma unroll
    for (int i = 0; i < 8; i++) {
        float4 o = make_float4(acc[i][0], acc[i][1], acc[i][2], acc[i][3]);
        *(float4*)(Cb + (long)(row0 + ty * 8 + i) * HWSZ + col0 + tx * 4) = o;
    }
}

// ---------------------------------------------------------------
// Depthwise 3x3 SAME (cross-correlation) + fused sum-of-squares for
// q,k channels (c < 384). grid: (W/32, H/8, BATCH*576), block (32,8)
// ---------------------------------------------------------------
__global__ __launch_bounds__(256) void dw_kernel(const float* __restrict__ wdw)
{
    const int bc = blockIdx.z;          // b*576 + c
    const int c  = bc % OC3;
    const int b  = bc / OC3;
    const float* p = g_qkv + (long)bc * HWSZ;
    float*       o = g_dw  + (long)bc * HWSZ;

    __shared__ float tile[10][34];
    const int x0 = blockIdx.x * 32, y0 = blockIdx.y * 8;
    const int tid = threadIdx.y * 32 + threadIdx.x;

    for (int i = tid; i < 340; i += 256) {
        int yy = i / 34, xx = i % 34;
        int gy = y0 + yy - 1, gx = x0 + xx - 1;
        tile[yy][xx] = (gy >= 0 && gy < HH && gx >= 0 && gx < WW)
                           ? p[gy * WW + gx] : 0.f;
    }
    __syncthreads();

    float wv[9];
#pragma unroll
    for (int i = 0; i < 9; i++) wv[i] = __ldg(&wdw[c * 9 + i]);

    const int tx = threadIdx.x, tyy = threadIdx.y;
    float s = 0.f;
#pragma unroll
    for (int dy = 0; dy < 3; dy++)
#pragma unroll
        for (int dx = 0; dx < 3; dx++)
            s = fmaf(wv[dy * 3 + dx], tile[tyy + dy][tx + dx], s);

    o[(y0 + tyy) * WW + x0 + tx] = s;

    if (c < 2 * CDIM) {   // q or k channel: accumulate sum of squares
        float ss = s * s;
#pragma unroll
        for (int off = 16; off > 0; off >>= 1)
            ss += __shfl_xor_sync(0xffffffffu, ss, off);
        __shared__ float wsum[8];
        int lane = tid & 31, wrp = tid >> 5;
        if (lane == 0) wsum[wrp] = ss;
        __syncthreads();
        if (tid == 0) {
            float tot = 0.f;
#pragma unroll
            for (int i = 0; i < 8; i++) tot += wsum[i];
            atomicAdd(&g_sumsq[b * 2 * CDIM + c], tot);
        }
    }
}

// ---------------------------------------------------------------
// attn_raw[b,h,d,e] += sum_n q[d,n]*k[e,n] over a 256-wide n chunk.
// 64 threads, 6x6 microtile (8x8 thread grid), smem sub-tiles of 64.
// grid: (HW/256, BATCH*NH)
// ---------------------------------------------------------------
__global__ __launch_bounds__(64) void attn_kernel()
{
    const int bh = blockIdx.y;
    const int b = bh >> 2, h = bh & 3;
    const float* qbase = g_dw + ((long)b * OC3 + h * HD) * HWSZ;
    const float* kbase = g_dw + ((long)b * OC3 + CDIM + h * HD) * HWSZ;
    const int n0 = blockIdx.x * 256;

    __shared__ float qs[HD][65];
    __shared__ float ks[HD][65];

    const int t = threadIdx.x;
    const int ty = t >> 3, tx = t & 7;
    const int d0 = ty * 6, e0 = tx * 6;

    float acc[6][6];
#pragma unroll
    for (int i = 0; i < 6; i++)
#pragma unroll
        for (int j = 0; j < 6; j++) acc[i][j] = 0.f;

    for (int sub = 0; sub < 4; sub++) {
        const int nb = n0 + sub * 64;
        __syncthreads();
        for (int i = t; i < HD * 64; i += 64) {
            int d = i >> 6, n = i & 63;
            qs[d][n] = qbase[(long)d * HWSZ + nb + n];
            ks[d][n] = kbase[(long)d * HWSZ + nb + n];
        }
        __syncthreads();
#pragma unroll 4
        for (int n = 0; n < 64; n++) {
            float qv[6], kv[6];
#pragma unroll
            for (int i = 0; i < 6; i++) qv[i] = qs[d0 + i][n];
#pragma unroll
            for (int j = 0; j < 6; j++) kv[j] = ks[e0 + j][n];
#pragma unroll
            for (int i = 0; i < 6; i++)
#pragma unroll
                for (int j = 0; j < 6; j++)
                    acc[i][j] = fmaf(qv[i], kv[j], acc[i][j]);
        }
    }

    float* ap = g_attn + (long)bh * HD * HD;
#pragma unroll
    for (int i = 0; i < 6; i++)
#pragma unroll
        for (int j = 0; j < 6; j++)
            atomicAdd(&ap[(d0 + i) * HD + e0 + j], acc[i][j]);
}

// ---------------------------------------------------------------
// normalize (l2 norms from sumsq), apply temperature, softmax rows.
// grid: BATCH*NH blocks, 64 threads (48 active, one row each)
// ---------------------------------------------------------------
__global__ void softmax_kernel(const float* __restrict__ log_temp)
{
    const int bh = blockIdx.x;
    const int b = bh >> 2, h = bh & 3;
    __shared__ float nq[HD], nk[HD];
    const int t = threadIdx.x;
    if (t < HD) {
        nq[t] = fmaxf(sqrtf(g_sumsq[b * 2 * CDIM + h * HD + t]), 1e-12f);
        nk[t] = fmaxf(sqrtf(g_sumsq[b * 2 * CDIM + CDIM + h * HD + t]), 1e-12f);
    }
    __syncthreads();
    const float temp = log1pf(expf(log_temp[h])) + 1e-6f;
    if (t < HD) {
        float v[HD];
        float mx = -1e30f;
        const float inq = temp / nq[t];
        const float* row = g_attn + ((long)bh * HD + t) * HD;
#pragma unroll 8
        for (int e = 0; e < HD; e++) {
            float a = row[e] * inq / nk[e];
            v[e] = a;
            mx = fmaxf(mx, a);
        }
        float ssum = 0.f;
#pragma unroll 8
        for (int e = 0; e < HD; e++) { v[e] = __expf(v[e] - mx); ssum += v[e]; }
        const float inv = 1.f / ssum;
        float* orow = g_attn_s + ((long)bh * HD + t) * HD;
#pragma unroll 8
        for (int e = 0; e < HD; e++) orow[e] = v[e] * inv;
    }
}

// ---------------------------------------------------------------
// W2[b,o,h*48+e] = sum_d w_proj[o, h*48+d] * attn_s[b,h,d,e]
// grid: BATCH*CDIM blocks, 192 threads (one output each)
// ---------------------------------------------------------------
__global__ void w2_kernel(const float* __restrict__ w_proj)
{
    const int bo = blockIdx.x;
    const int b = bo / CDIM, o = bo % CDIM;
    const int he = threadIdx.x;
    const int h = he / HD, e = he % HD;
    const float* wp = w_proj + o * CDIM + h * HD;
    const float* at = g_attn_s + ((long)(b * NH + h) * HD) * HD + e;
    float s = 0.f;
#pragma unroll 8
    for (int d = 0; d < HD; d++) s = fmaf(wp[d], at[d * HD], s);
    g_W2[((long)b * CDIM + o) * CDIM + he] = s;
}

// ---------------------------------------------------------------
extern "C" void kernel_launch(void* const* d_in, const int* in_sizes, int n_in,
                              void* d_out, int out_size)
{
    const float* x      = (const float*)d_in[0];
    const float* w_qkv  = (const float*)d_in[1];
    const float* w_dw   = (const float*)d_in[2];
    const float* w_proj = (const float*)d_in[3];
    const float* ltemp  = (const float*)d_in[4];
    float* out = (float*)d_out;

    float *p_qkv, *p_dw, *p_W2;
    cudaGetSymbolAddress((void**)&p_qkv, g_qkv);
    cudaGetSymbolAddress((void**)&p_dw,  g_dw);
    cudaGetSymbolAddress((void**)&p_W2,  g_W2);

    zero_kernel<<<72, 256>>>();

    // GEMM1: qkv = w_qkv @ x        [576, HW] per batch
    sgemm_kernel<<<dim3(HWSZ / 128, OC3 / 64, BATCH), 256>>>(
        w_qkv, x, p_qkv, 0L, (long)CDIM * HWSZ, (long)OC3 * HWSZ);

    // depthwise 3x3 + q/k sum-of-squares
    dw_kernel<<<dim3(WW / 32, HH / 8, BATCH * OC3), dim3(32, 8)>>>(w_dw);

    // attn_raw = q @ k^T (atomically accumulated over n chunks)
    attn_kernel<<<dim3(HWSZ / 256, BATCH * NH), 64>>>();

    // normalize + temperature + softmax
    softmax_kernel<<<BATCH * NH, 64>>>(ltemp);

    // W2 = w_proj @ blockdiag(attn)
    w2_kernel<<<BATCH * CDIM, 192>>>(w_proj);

    // GEMM2: out = W2[b] @ v[b]     [192, HW] per batch  (v = channels 384..575)
    sgemm_kernel<<<dim3(HWSZ / 128, CDIM / 64, BATCH), 256>>>(
        p_W2, p_dw + (long)2 * CDIM * HWSZ, out,
        (long)CDIM * CDIM, (long)OC3 * HWSZ, (long)CDIM * HWSZ);
}

// round 2
// speedup vs baseline: 1.0283x; 1.0283x over previous
#include <cuda_runtime.h>
#include <math.h>

#define BATCH 2
#define CDIM 192
#define HH 192
#define WW 192
#define HWSZ (HH*WW)      // 36864
#define OC3 (3*CDIM)      // 576
#define NH 4
#define HD 48

// ---- scratch (device globals; no allocations allowed) ----
__device__ float g_qkv[(long)BATCH*OC3*HWSZ];   // after 1x1 conv
__device__ float g_dw [(long)BATCH*OC3*HWSZ];   // after depthwise conv
__device__ float g_sumsq[BATCH*2*CDIM];          // per-channel sum of squares (q,k)
__device__ float g_attn [BATCH*NH*HD*HD];        // raw q.k^T accumulators
__device__ float g_attn_s[BATCH*NH*HD*HD];       // softmaxed
__device__ float g_W2[BATCH*CDIM*CDIM];          // w_proj @ blockdiag(attn)

__device__ __forceinline__ float cvt_tf32(float x) {
    unsigned u;
    asm("cvt.rna.tf32.f32 %0, %1;" : "=r"(u) : "f"(x));
    return __uint_as_float(u);
}

// ---------------------------------------------------------------
// zero the atomic accumulators (graph replays need this each call)
// ---------------------------------------------------------------
__global__ void zero_kernel() {
    int i = blockIdx.x * blockDim.x + threadIdx.x;
    if (i < BATCH*2*CDIM)    g_sumsq[i] = 0.f;
    if (i < BATCH*NH*HD*HD)  g_attn[i]  = 0.f;
}

// ---------------------------------------------------------------
// TF32 tensor-core GEMM: C[M,HW] = A[M,192] @ B[192,HW], row-major.
// Block tile 64x256, BK=32, 256 threads (8 warps, 2x4), warp 32x64.
// mma.sync.aligned.m16n8k8 tf32. grid: (HW/256, M/64, BATCH)
// ---------------------------------------------------------------
__global__ __launch_bounds__(256) void tf32_gemm_kernel(
    const float* __restrict__ A, const float* __restrict__ Bm, float* __restrict__ Cm,
    long aStride, long bStride, long cStride)
{
    __shared__ float As[32][68];        // As[k][m]
    __shared__ float Bs[32][260];       // Bs[k][n], padded

    const int t = threadIdx.x;
    const float* Ab = A  + (long)blockIdx.z * aStride + (long)blockIdx.y * 64 * 192;
    const float* Bb = Bm + (long)blockIdx.z * bStride + blockIdx.x * 256;
    float*       Cb = Cm + (long)blockIdx.z * cStride;

    // loader coords
    const int am0 = (t * 2)     >> 3, akq0 = (t * 2)     & 7;
    const int am1 = (t * 2 + 1) >> 3, akq1 = (t * 2 + 1) & 7;
    const int n4 = t & 63, kr = t >> 6;

    // compute coords
    const int w = t >> 5, l = t & 31;
    const int mw = (w >> 2) * 32;       // 0 or 32
    const int nw = (w & 3) * 64;
    const int g = l >> 2, q = l & 3;

    float4 aReg[2];
    float4 bReg[8];
    float acc[2][8][4];
#pragma unroll
    for (int mt = 0; mt < 2; mt++)
#pragma unroll
        for (int nt = 0; nt < 8; nt++)
#pragma unroll
            for (int c = 0; c < 4; c++) acc[mt][nt][c] = 0.f;

    // prefetch tile 0
    aReg[0] = *(const float4*)(Ab + (long)am0 * 192 + akq0 * 4);
    aReg[1] = *(const float4*)(Ab + (long)am1 * 192 + akq1 * 4);
#pragma unroll
    for (int i = 0; i < 8; i++)
        bReg[i] = *(const float4*)(Bb + (long)(kr * 8 + i) * HWSZ + n4 * 4);

    for (int kt = 0; kt < 6; kt++) {
        // store (tf32-rounded) to smem
        As[akq0*4+0][am0] = cvt_tf32(aReg[0].x);
        As[akq0*4+1][am0] = cvt_tf32(aReg[0].y);
        As[akq0*4+2][am0] = cvt_tf32(aReg[0].z);
        As[akq0*4+3][am0] = cvt_tf32(aReg[0].w);
        As[akq1*4+0][am1] = cvt_tf32(aReg[1].x);
        As[akq1*4+1][am1] = cvt_tf32(aReg[1].y);
        As[akq1*4+2][am1] = cvt_tf32(aReg[1].z);
        As[akq1*4+3][am1] = cvt_tf32(aReg[1].w);
#pragma unroll
        for (int i = 0; i < 8; i++) {
            float4 v = bReg[i];
            v.x = cvt_tf32(v.x); v.y = cvt_tf32(v.y);
            v.z = cvt_tf32(v.z); v.w = cvt_tf32(v.w);
            *(float4*)&Bs[kr * 8 + i][n4 * 4] = v;
        }
        __syncthreads();

        if (kt < 5) {   // issue next tile's global loads (overlap with compute)
            const int k0 = (kt + 1) * 32;
            aReg[0] = *(const float4*)(Ab + (long)am0 * 192 + k0 + akq0 * 4);
            aReg[1] = *(const float4*)(Ab + (long)am1 * 192 + k0 + akq1 * 4);
#pragma unroll
            for (int i = 0; i < 8; i++)
                bReg[i] = *(const float4*)(Bb + (long)(k0 + kr * 8 + i) * HWSZ + n4 * 4);
        }

#pragma unroll
        for (int s = 0; s < 4; s++) {
            const int kb = s * 8;
            unsigned a[2][4], bf[8][2];
#pragma unroll
            for (int mt = 0; mt < 2; mt++) {
                a[mt][0] = __float_as_uint(As[kb + q    ][mw + mt*16 + g    ]);
                a[mt][1] = __float_as_uint(As[kb + q    ][mw + mt*16 + g + 8]);
                a[mt][2] = __float_as_uint(As[kb + q + 4][mw + mt*16 + g    ]);
                a[mt][3] = __float_as_uint(As[kb + q + 4][mw + mt*16 + g + 8]);
            }
#pragma unroll
            for (int nt = 0; nt < 8; nt++) {
                bf[nt][0] = __float_as_uint(Bs[kb + q    ][nw + nt*8 + g]);
                bf[nt][1] = __float_as_uint(Bs[kb + q + 4][nw + nt*8 + g]);
            }
#pragma unroll
            for (int mt = 0; mt < 2; mt++)
#pragma unroll
                for (int nt = 0; nt < 8; nt++) {
                    float* d = acc[mt][nt];
                    asm volatile(
                        "mma.sync.aligned.m16n8k8.row.col.f32.tf32.tf32.f32 "
                        "{%0,%1,%2,%3}, {%4,%5,%6,%7}, {%8,%9}, {%0,%1,%2,%3};\n"
                        : "+f"(d[0]), "+f"(d[1]), "+f"(d[2]), "+f"(d[3])
                        : "r"(a[mt][0]), "r"(a[mt][1]), "r"(a[mt][2]), "r"(a[mt][3]),
                          "r"(bf[nt][0]), "r"(bf[nt][1]));
                }
        }
        __syncthreads();
    }

    // write C (float2 per fragment half)
    const int colb = blockIdx.x * 256 + nw;
    const int rowb = blockIdx.y * 64 + mw;
#pragma unroll
    for (int mt = 0; mt < 2; mt++)
#pragma unroll
        for (int nt = 0; nt < 8; nt++) {
            const int row = rowb + mt * 16 + g;
            const int col = colb + nt * 8 + 2 * q;
            *(float2*)(Cb + (long)row * HWSZ + col) =
                make_float2(acc[mt][nt][0], acc[mt][nt][1]);
            *(float2*)(Cb + (long)(row + 8) * HWSZ + col) =
                make_float2(acc[mt][nt][2], acc[mt][nt][3]);
        }
}

// ---------------------------------------------------------------
// Depthwise 3x3 SAME (cross-correlation) + fused sum-of-squares for
// q,k channels (c < 384). grid: (W/32, H/8, BATCH*576), block (32,8)
// ---------------------------------------------------------------
__global__ __launch_bounds__(256) void dw_kernel(const float* __restrict__ wdw)
{
    const int bc = blockIdx.z;          // b*576 + c
    const int c  = bc % OC3;
    const int b  = bc / OC3;
    const float* p = g_qkv + (long)bc * HWSZ;
    float*       o = g_dw  + (long)bc * HWSZ;

    __shared__ float tile[10][34];
    const int x0 = blockIdx.x * 32, y0 = blockIdx.y * 8;
    const int tid = threadIdx.y * 32 + threadIdx.x;

    for (int i = tid; i < 340; i += 256) {
        int yy = i / 34, xx = i % 34;
        int gy = y0 + yy - 1, gx = x0 + xx - 1;
        tile[yy][xx] = (gy >= 0 && gy < HH && gx >= 0 && gx < WW)
                           ? p[gy * WW + gx] : 0.f;
    }
    __syncthreads();

    float wv[9];
#pragma unroll
    for (int i = 0; i < 9; i++) wv[i] = __ldg(&wdw[c * 9 + i]);

    const int tx = threadIdx.x, tyy = threadIdx.y;
    float s = 0.f;
#pragma unroll
    for (int dy = 0; dy < 3; dy++)
#pragma unroll
        for (int dx = 0; dx < 3; dx++)
            s = fmaf(wv[dy * 3 + dx], tile[tyy + dy][tx + dx], s);

    o[(y0 + tyy) * WW + x0 + tx] = s;

    if (c < 2 * CDIM) {   // q or k channel: accumulate sum of squares
        float ss = s * s;
#pragma unroll
        for (int off = 16; off > 0; off >>= 1)
            ss += __shfl_xor_sync(0xffffffffu, ss, off);
        __shared__ float wsum[8];
        int lane = tid & 31, wrp = tid >> 5;
        if (lane == 0) wsum[wrp] = ss;
        __syncthreads();
        if (tid == 0) {
            float tot = 0.f;
#pragma unroll
            for (int i = 0; i < 8; i++) tot += wsum[i];
            atomicAdd(&g_sumsq[b * 2 * CDIM + c], tot);
        }
    }
}

// ---------------------------------------------------------------
// attn_raw[b,h,d,e] += sum_n q[d,n]*k[e,n] over a 96-wide n chunk.
// 128 threads = 2 groups of 64; each group a 48-wide n sub-slice,
// 6x6 microtile per thread. smem stride 101 -> conflict-free.
// grid: (HW/96, BATCH*NH)
// ---------------------------------------------------------------
#define ANC 96
__global__ __launch_bounds__(128) void attn_kernel()
{
    const int bh = blockIdx.y;
    const int b = bh >> 2, h = bh & 3;
    const float* qbase = g_dw + ((long)b * OC3 + h * HD) * HWSZ;
    const float* kbase = g_dw + ((long)b * OC3 + CDIM + h * HD) * HWSZ;
    const int n0 = blockIdx.x * ANC;

    __shared__ float qs[HD][ANC + 5];   // stride 101: 101%32=5 -> conflict-free reads
    __shared__ float ks[HD][ANC + 5];

    const int t = threadIdx.x;
    // load 48 x 96 floats per tensor = 48 x 24 float4
    for (int idx = t; idx < HD * 24; idx += 128) {
        int d = idx / 24, nq = idx % 24;
        float4 v = *(const float4*)(qbase + (long)d * HWSZ + n0 + nq * 4);
        qs[d][nq*4+0] = v.x; qs[d][nq*4+1] = v.y;
        qs[d][nq*4+2] = v.z; qs[d][nq*4+3] = v.w;
        float4 u = *(const float4*)(kbase + (long)d * HWSZ + n0 + nq * 4);
        ks[d][nq*4+0] = u.x; ks[d][nq*4+1] = u.y;
        ks[d][nq*4+2] = u.z; ks[d][nq*4+3] = u.w;
    }
    __syncthreads();

    const int grp = t >> 6, tl = t & 63;
    const int d0 = (tl >> 3) * 6, e0 = (tl & 7) * 6;
    const int nb = grp * 48;

    float acc[6][6];
#pragma unroll
    for (int i = 0; i < 6; i++)
#pragma unroll
        for (int j = 0; j < 6; j++) acc[i][j] = 0.f;

#pragma unroll 4
    for (int n = 0; n < 48; n++) {
        float qv[6], kv[6];
#pragma unroll
        for (int i = 0; i < 6; i++) qv[i] = qs[d0 + i][nb + n];
#pragma unroll
        for (int j = 0; j < 6; j++) kv[j] = ks[e0 + j][nb + n];
#pragma unroll
        for (int i = 0; i < 6; i++)
#pragma unroll
            for (int j = 0; j < 6; j++)
                acc[i][j] = fmaf(qv[i], kv[j], acc[i][j]);
    }

    float* ap = g_attn + (long)bh * HD * HD;
#pragma unroll
    for (int i = 0; i < 6; i++)
#pragma unroll
        for (int j = 0; j < 6; j++)
            atomicAdd(&ap[(d0 + i) * HD + e0 + j], acc[i][j]);
}

// ---------------------------------------------------------------
// normalize (l2 norms from sumsq), apply temperature, softmax rows.
// grid: BATCH*NH blocks, 64 threads (48 active, one row each)
// ---------------------------------------------------------------
__global__ void softmax_kernel(const float* __restrict__ log_temp)
{
    const int bh = blockIdx.x;
    const int b = bh >> 2, h = bh & 3;
    __shared__ float nq[HD], nk[HD];
    const int t = threadIdx.x;
    if (t < HD) {
        nq[t] = fmaxf(sqrtf(g_sumsq[b * 2 * CDIM + h * HD + t]), 1e-12f);
        nk[t] = fmaxf(sqrtf(g_sumsq[b * 2 * CDIM + CDIM + h * HD + t]), 1e-12f);
    }
    __syncthreads();
    const float temp = log1pf(expf(log_temp[h])) + 1e-6f;
    if (t < HD) {
        float v[HD];
        float mx = -1e30f;
        const float inq = temp / nq[t];
        const float* row = g_attn + ((long)bh * HD + t) * HD;
#pragma unroll 8
        for (int e = 0; e < HD; e++) {
            float a = row[e] * inq / nk[e];
            v[e] = a;
            mx = fmaxf(mx, a);
        }
        float ssum = 0.f;
#pragma unroll 8
        for (int e = 0; e < HD; e++) { v[e] = __expf(v[e] - mx); ssum += v[e]; }
        const float inv = 1.f / ssum;
        float* orow = g_attn_s + ((long)bh * HD + t) * HD;
#pragma unroll 8
        for (int e = 0; e < HD; e++) orow[e] = v[e] * inv;
    }
}

// ---------------------------------------------------------------
// W2[b,o,h*48+e] = sum_d w_proj[o, h*48+d] * attn_s[b,h,d,e]
// grid: BATCH*CDIM blocks, 192 threads (one output each)
// ---------------------------------------------------------------
__global__ void w2_kernel(const float* __restrict__ w_proj)
{
    const int bo = blockIdx.x;
    const int b = bo / CDIM, o = bo % CDIM;
    const int he = threadIdx.x;
    const int h = he / HD, e = he % HD;
    const float* wp = w_proj + o * CDIM + h * HD;
    const float* at = g_attn_s + ((long)(b * NH + h) * HD) * HD + e;
    float s = 0.f;
#pragma unroll 8
    for (int d = 0; d < HD; d++) s = fmaf(wp[d], at[d * HD], s);
    g_W2[((long)b * CDIM + o) * CDIM + he] = s;
}

// ---------------------------------------------------------------
extern "C" void kernel_launch(void* const* d_in, const int* in_sizes, int n_in,
                              void* d_out, int out_size)
{
    const float* x      = (const float*)d_in[0];
    const float* w_qkv  = (const float*)d_in[1];
    const float* w_dw   = (const float*)d_in[2];
    const float* w_proj = (const float*)d_in[3];
    const float* ltemp  = (const float*)d_in[4];
    float* out = (float*)d_out;

    float *p_qkv, *p_dw, *p_W2;
    cudaGetSymbolAddress((void**)&p_qkv, g_qkv);
    cudaGetSymbolAddress((void**)&p_dw,  g_dw);
    cudaGetSymbolAddress((void**)&p_W2,  g_W2);

    zero_kernel<<<72, 256>>>();

    // GEMM1: qkv = w_qkv @ x        [576, HW] per batch (tf32 tensor cores)
    tf32_gemm_kernel<<<dim3(HWSZ / 256, OC3 / 64, BATCH), 256>>>(
        w_qkv, x, p_qkv, 0L, (long)CDIM * HWSZ, (long)OC3 * HWSZ);

    // depthwise 3x3 + q/k sum-of-squares
    dw_kernel<<<dim3(WW / 32, HH / 8, BATCH * OC3), dim3(32, 8)>>>(w_dw);

    // attn_raw = q @ k^T (atomically accumulated over n chunks)
    attn_kernel<<<dim3(HWSZ / ANC, BATCH * NH), 128>>>();

    // normalize + temperature + softmax
    softmax_kernel<<<BATCH * NH, 64>>>(ltemp);

    // W2 = w_proj @ blockdiag(attn)
    w2_kernel<<<BATCH * CDIM, 192>>>(w_proj);

    // GEMM2: out = W2[b] @ v[b]     [192, HW] per batch (tf32 tensor cores)
    tf32_gemm_kernel<<<dim3(HWSZ / 256, CDIM / 64, BATCH), 256>>>(
        p_W2, p_dw + (long)2 * CDIM * HWSZ, out,
        (long)CDIM * CDIM, (long)OC3 * HWSZ, (long)CDIM * HWSZ);
}

// round 4
// speedup vs baseline: 1.1136x; 1.0830x over previous
#include <cuda_runtime.h>
#include <math.h>

#define BATCH 2
#define CDIM 192
#define HH 192
#define WW 192
#define HWSZ (HH*WW)      // 36864
#define OC3 (3*CDIM)      // 576
#define NH 4
#define HD 48
#define ACH 24            // attn K-reduction chunks per (b,h)

// ---- scratch (device globals; no allocations allowed) ----
__device__ float g_qkv[(long)BATCH*OC3*HWSZ];   // after 1x1 conv
__device__ float g_dw [(long)BATCH*OC3*HWSZ];   // after depthwise conv
__device__ float g_sumsq[BATCH*2*CDIM];          // per-channel sum of squares (q,k)
__device__ float g_attn_part[BATCH*NH*ACH*HD*HD]; // per-chunk partial q.k^T
__device__ float g_attn_s[BATCH*NH*HD*HD];       // softmaxed
__device__ float g_W2[BATCH*CDIM*CDIM];          // w_proj @ blockdiag(attn)

__device__ __forceinline__ float cvt_tf32(float x) {
    unsigned u;
    asm("cvt.rna.tf32.f32 %0, %1;" : "=r"(u) : "f"(x));
    return __uint_as_float(u);
}

// ---------------------------------------------------------------
// zero ALL 768 sumsq accumulators each call (graph replays!)
// ---------------------------------------------------------------
__global__ void zero_kernel() {
    int i = blockIdx.x * blockDim.x + threadIdx.x;
    if (i < BATCH*2*CDIM) g_sumsq[i] = 0.f;
}

// ---------------------------------------------------------------
// TF32 tensor-core GEMM: C[M,HW] = A[M,192] @ B[192,HW], row-major.
// Block tile 64x256, BK=32, 256 threads (8 warps, 2x4), warp 32x64.
// smem strides == 8 (mod 32) -> conflict-free fragment LDS.
// ---------------------------------------------------------------
__global__ __launch_bounds__(256) void tf32_gemm_kernel(
    const float* __restrict__ A, const float* __restrict__ Bm, float* __restrict__ Cm,
    long aStride, long bStride, long cStride)
{
    __shared__ float As[32][72];        // As[k][m], 72%32==8
    __shared__ float Bs[32][264];       // Bs[k][n], 264%32==8

    const int t = threadIdx.x;
    const float* Ab = A  + (long)blockIdx.z * aStride + (long)blockIdx.y * 64 * 192;
    const float* Bb = Bm + (long)blockIdx.z * bStride + blockIdx.x * 256;
    float*       Cb = Cm + (long)blockIdx.z * cStride;

    const int am0 = (t * 2)     >> 3, akq0 = (t * 2)     & 7;
    const int am1 = (t * 2 + 1) >> 3, akq1 = (t * 2 + 1) & 7;
    const int n4 = t & 63, kr = t >> 6;

    const int w = t >> 5, l = t & 31;
    const int mw = (w >> 2) * 32;
    const int nw = (w & 3) * 64;
    const int g = l >> 2, q = l & 3;

    float4 aReg[2];
    float4 bReg[8];
    float acc[2][8][4];
#pragma unroll
    for (int mt = 0; mt < 2; mt++)
#pragma unroll
        for (int nt = 0; nt < 8; nt++)
#pragma unroll
            for (int c = 0; c < 4; c++) acc[mt][nt][c] = 0.f;

    aReg[0] = *(const float4*)(Ab + (long)am0 * 192 + akq0 * 4);
    aReg[1] = *(const float4*)(Ab + (long)am1 * 192 + akq1 * 4);
#pragma unroll
    for (int i = 0; i < 8; i++)
        bReg[i] = *(const float4*)(Bb + (long)(kr * 8 + i) * HWSZ + n4 * 4);

    for (int kt = 0; kt < 6; kt++) {
        As[akq0*4+0][am0] = cvt_tf32(aReg[0].x);
        As[akq0*4+1][am0] = cvt_tf32(aReg[0].y);
        As[akq0*4+2][am0] = cvt_tf32(aReg[0].z);
        As[akq0*4+3][am0] = cvt_tf32(aReg[0].w);
        As[akq1*4+0][am1] = cvt_tf32(aReg[1].x);
        As[akq1*4+1][am1] = cvt_tf32(aReg[1].y);
        As[akq1*4+2][am1] = cvt_tf32(aReg[1].z);
        As[akq1*4+3][am1] = cvt_tf32(aReg[1].w);
#pragma unroll
        for (int i = 0; i < 8; i++) {
            float4 v = bReg[i];
            v.x = cvt_tf32(v.x); v.y = cvt_tf32(v.y);
            v.z = cvt_tf32(v.z); v.w = cvt_tf32(v.w);
            *(float4*)&Bs[kr * 8 + i][n4 * 4] = v;
        }
        __syncthreads();

        if (kt < 5) {
            const int k0 = (kt + 1) * 32;
            aReg[0] = *(const float4*)(Ab + (long)am0 * 192 + k0 + akq0 * 4);
            aReg[1] = *(const float4*)(Ab + (long)am1 * 192 + k0 + akq1 * 4);
#pragma unroll
            for (int i = 0; i < 8; i++)
                bReg[i] = *(const float4*)(Bb + (long)(k0 + kr * 8 + i) * HWSZ + n4 * 4);
        }

#pragma unroll
        for (int s = 0; s < 4; s++) {
            const int kb = s * 8;
            unsigned a[2][4], bf[8][2];
#pragma unroll
            for (int mt = 0; mt < 2; mt++) {
                a[mt][0] = __float_as_uint(As[kb + q    ][mw + mt*16 + g    ]);
                a[mt][1] = __float_as_uint(As[kb + q    ][mw + mt*16 + g + 8]);
                a[mt][2] = __float_as_uint(As[kb + q + 4][mw + mt*16 + g    ]);
                a[mt][3] = __float_as_uint(As[kb + q + 4][mw + mt*16 + g + 8]);
            }
#pragma unroll
            for (int nt = 0; nt < 8; nt++) {
                bf[nt][0] = __float_as_uint(Bs[kb + q    ][nw + nt*8 + g]);
                bf[nt][1] = __float_as_uint(Bs[kb + q + 4][nw + nt*8 + g]);
            }
#pragma unroll
            for (int mt = 0; mt < 2; mt++)
#pragma unroll
                for (int nt = 0; nt < 8; nt++) {
                    float* d = acc[mt][nt];
                    asm volatile(
                        "mma.sync.aligned.m16n8k8.row.col.f32.tf32.tf32.f32 "
                        "{%0,%1,%2,%3}, {%4,%5,%6,%7}, {%8,%9}, {%0,%1,%2,%3};\n"
                        : "+f"(d[0]), "+f"(d[1]), "+f"(d[2]), "+f"(d[3])
                        : "r"(a[mt][0]), "r"(a[mt][1]), "r"(a[mt][2]), "r"(a[mt][3]),
                          "r"(bf[nt][0]), "r"(bf[nt][1]));
                }
        }
        __syncthreads();
    }

    const int colb = blockIdx.x * 256 + nw;
    const int rowb = blockIdx.y * 64 + mw;
#pragma unroll
    for (int mt = 0; mt < 2; mt++)
#pragma unroll
        for (int nt = 0; nt < 8; nt++) {
            const int row = rowb + mt * 16 + g;
            const int col = colb + nt * 8 + 2 * q;
            *(float2*)(Cb + (long)row * HWSZ + col) =
                make_float2(acc[mt][nt][0], acc[mt][nt][1]);
            *(float2*)(Cb + (long)(row + 8) * HWSZ + col) =
                make_float2(acc[mt][nt][2], acc[mt][nt][3]);
        }
}

// ---------------------------------------------------------------
// Depthwise 3x3 SAME + fused sum-of-squares for q,k channels.
// ---------------------------------------------------------------
__global__ __launch_bounds__(256) void dw_kernel(const float* __restrict__ wdw)
{
    const int bc = blockIdx.z;
    const int c  = bc % OC3;
    const int b  = bc / OC3;
    const float* p = g_qkv + (long)bc * HWSZ;
    float*       o = g_dw  + (long)bc * HWSZ;

    __shared__ float tile[10][34];
    const int x0 = blockIdx.x * 32, y0 = blockIdx.y * 8;
    const int tid = threadIdx.y * 32 + threadIdx.x;

    for (int i = tid; i < 340; i += 256) {
        int yy = i / 34, xx = i % 34;
        int gy = y0 + yy - 1, gx = x0 + xx - 1;
        tile[yy][xx] = (gy >= 0 && gy < HH && gx >= 0 && gx < WW)
                           ? p[gy * WW + gx] : 0.f;
    }
    __syncthreads();

    float wv[9];
#pragma unroll
    for (int i = 0; i < 9; i++) wv[i] = __ldg(&wdw[c * 9 + i]);

    const int tx = threadIdx.x, tyy = threadIdx.y;
    float s = 0.f;
#pragma unroll
    for (int dy = 0; dy < 3; dy++)
#pragma unroll
        for (int dx = 0; dx < 3; dx++)
            s = fmaf(wv[dy * 3 + dx], tile[tyy + dy][tx + dx], s);

    o[(y0 + tyy) * WW + x0 + tx] = s;

    if (c < 2 * CDIM) {
        float ss = s * s;
#pragma unroll
        for (int off = 16; off > 0; off >>= 1)
            ss += __shfl_xor_sync(0xffffffffu, ss, off);
        __shared__ float wsum[8];
        int lane = tid & 31, wrp = tid >> 5;
        if (lane == 0) wsum[wrp] = ss;
        __syncthreads();
        if (tid == 0) {
            float tot = 0.f;
#pragma unroll
            for (int i = 0; i < 8; i++) tot += wsum[i];
            atomicAdd(&g_sumsq[b * 2 * CDIM + c], tot);
        }
    }
}

// ---------------------------------------------------------------
// attn partials: block (chunk, bh) reduces 1536 n-columns into a
// 48x48 partial tile. 256 threads = 16 n-groups x 16 threads; each
// thread owns a 12x12 microtile; group-combine in smem; NO atomics.
// grid: (ACH, BATCH*NH), block 256
// ---------------------------------------------------------------
__global__ __launch_bounds__(256) void attn_kernel()
{
    const int bh = blockIdx.y;
    const int b = bh >> 2, h = bh & 3;
    const float* qbase = g_dw + ((long)b * OC3 + h * HD) * HWSZ;
    const float* kbase = g_dw + ((long)b * OC3 + CDIM + h * HD) * HWSZ;
    const int nblk = blockIdx.x * (HWSZ / ACH);   // 1536 n per block

    __shared__ float qs[HD][101];
    __shared__ float ks[HD][101];
    __shared__ float buf[HD * HD];

    const int t = threadIdx.x;
    const int grp = t >> 4;             // 0..15 : n-slice within 96-tile
    const int sub = t & 15;
    const int d0 = (sub >> 2) * 12;
    const int e0 = (sub & 3) * 12;

    float acc[12][12];
#pragma unroll
    for (int i = 0; i < 12; i++)
#pragma unroll
        for (int j = 0; j < 12; j++) acc[i][j] = 0.f;

    for (int it = 0; it < 16; it++) {   // 16 x 96 = 1536 columns
        const int n0 = nblk + it * 96;
        __syncthreads();
        for (int idx = t; idx < HD * 24; idx += 256) {
            int d = idx / 24, nq = idx % 24;
            float4 v = *(const float4*)(qbase + (long)d * HWSZ + n0 + nq * 4);
            qs[d][nq*4+0] = v.x; qs[d][nq*4+1] = v.y;
            qs[d][nq*4+2] = v.z; qs[d][nq*4+3] = v.w;
            float4 u = *(const float4*)(kbase + (long)d * HWSZ + n0 + nq * 4);
            ks[d][nq*4+0] = u.x; ks[d][nq*4+1] = u.y;
            ks[d][nq*4+2] = u.z; ks[d][nq*4+3] = u.w;
        }
        __syncthreads();

        const int nb = grp * 6;         // 6 columns per group
#pragma unroll
        for (int n = 0; n < 6; n++) {
            float qv[12], kv[12];
#pragma unroll
            for (int i = 0; i < 12; i++) qv[i] = qs[d0 + i][nb + n];
#pragma unroll
            for (int j = 0; j < 12; j++) kv[j] = ks[e0 + j][nb + n];
#pragma unroll
            for (int i = 0; i < 12; i++)
#pragma unroll
                for (int j = 0; j < 12; j++)
                    acc[i][j] = fmaf(qv[i], kv[j], acc[i][j]);
        }
    }

    // combine the 16 group partials in smem (no atomics)
    __syncthreads();
    for (int r = 0; r < 16; r++) {
        if (grp == r) {
#pragma unroll
            for (int i = 0; i < 12; i++)
#pragma unroll
                for (int j = 0; j < 12; j++) {
                    int cell = (d0 + i) * HD + e0 + j;
                    if (r == 0) buf[cell] = acc[i][j];
                    else        buf[cell] += acc[i][j];
                }
        }
        __syncthreads();
    }

    float* op = g_attn_part + ((long)bh * ACH + blockIdx.x) * HD * HD;
    for (int idx = t; idx < HD * HD; idx += 256) op[idx] = buf[idx];
}

// ---------------------------------------------------------------
// reduce partials, normalize, temperature, softmax rows.
// grid: BATCH*NH blocks, 64 threads (48 active, one row each)
// ---------------------------------------------------------------
__global__ void softmax_kernel(const float* __restrict__ log_temp)
{
    const int bh = blockIdx.x;
    const int b = bh >> 2, h = bh & 3;
    __shared__ float nq[HD], nk[HD];
    const int t = threadIdx.x;
    if (t < HD) {
        nq[t] = fmaxf(sqrtf(g_sumsq[b * 2 * CDIM + h * HD + t]), 1e-12f);
        nk[t] = fmaxf(sqrtf(g_sumsq[b * 2 * CDIM + CDIM + h * HD + t]), 1e-12f);
    }
    __syncthreads();
    const float temp = log1pf(expf(log_temp[h])) + 1e-6f;
    if (t < HD) {
        float v[HD];
        const float* pp = g_attn_part + (long)bh * ACH * HD * HD + t * HD;
#pragma unroll 4
        for (int e = 0; e < HD; e++) v[e] = 0.f;
        for (int c = 0; c < ACH; c++) {
            const float* row = pp + c * HD * HD;
#pragma unroll 8
            for (int e = 0; e < HD; e++) v[e] += row[e];
        }
        float mx = -1e30f;
        const float inq = temp / nq[t];
#pragma unroll 8
        for (int e = 0; e < HD; e++) {
            v[e] = v[e] * inq / nk[e];
            mx = fmaxf(mx, v[e]);
        }
        float ssum = 0.f;
#pragma unroll 8
        for (int e = 0; e < HD; e++) { v[e] = __expf(v[e] - mx); ssum += v[e]; }
        const float inv = 1.f / ssum;
        float* orow = g_attn_s + ((long)bh * HD + t) * HD;
#pragma unroll 8
        for (int e = 0; e < HD; e++) orow[e] = v[e] * inv;
    }
}

// ---------------------------------------------------------------
// W2[b,o,h*48+e] = sum_d w_proj[o, h*48+d] * attn_s[b,h,d,e]
// ---------------------------------------------------------------
__global__ void w2_kernel(const float* __restrict__ w_proj)
{
    const int bo = blockIdx.x;
    const int b = bo / CDIM, o = bo % CDIM;
    const int he = threadIdx.x;
    const int h = he / HD, e = he % HD;
    const float* wp = w_proj + o * CDIM + h * HD;
    const float* at = g_attn_s + ((long)(b * NH + h) * HD) * HD + e;
    float s = 0.f;
#pragma unroll 8
    for (int d = 0; d < HD; d++) s = fmaf(wp[d], at[d * HD], s);
    g_W2[((long)b * CDIM + o) * CDIM + he] = s;
}

// ---------------------------------------------------------------
extern "C" void kernel_launch(void* const* d_in, const int* in_sizes, int n_in,
                              void* d_out, int out_size)
{
    const float* x      = (const float*)d_in[0];
    const float* w_qkv  = (const float*)d_in[1];
    const float* w_dw   = (const float*)d_in[2];
    const float* w_proj = (const float*)d_in[3];
    const float* ltemp  = (const float*)d_in[4];
    float* out = (float*)d_out;

    float *p_qkv, *p_dw, *p_W2;
    cudaGetSymbolAddress((void**)&p_qkv, g_qkv);
    cudaGetSymbolAddress((void**)&p_dw,  g_dw);
    cudaGetSymbolAddress((void**)&p_W2,  g_W2);

    zero_kernel<<<3, 256>>>();   // 768 elements — MUST cover all of g_sumsq

    // GEMM1: qkv = w_qkv @ x        [576, HW] per batch (tf32 tensor cores)
    tf32_gemm_kernel<<<dim3(HWSZ / 256, OC3 / 64, BATCH), 256>>>(
        w_qkv, x, p_qkv, 0L, (long)CDIM * HWSZ, (long)OC3 * HWSZ);

    // depthwise 3x3 + q/k sum-of-squares
    dw_kernel<<<dim3(WW / 32, HH / 8, BATCH * OC3), dim3(32, 8)>>>(w_dw);

    // attn partials (no atomics)
    attn_kernel<<<dim3(ACH, BATCH * NH), 256>>>();

    // reduce + normalize + temperature + softmax
    softmax_kernel<<<BATCH * NH, 64>>>(ltemp);

    // W2 = w_proj @ blockdiag(attn)
    w2_kernel<<<BATCH * CDIM, 192>>>(w_proj);

    // GEMM2: out = W2[b] @ v[b]     [192, HW] per batch (tf32 tensor cores)
    tf32_gemm_kernel<<<dim3(HWSZ / 256, CDIM / 64, BATCH), 256>>>(
        p_W2, p_dw + (long)2 * CDIM * HWSZ, out,
        (long)CDIM * CDIM, (long)OC3 * HWSZ, (long)CDIM * HWSZ);
}